// round 2
// baseline (speedup 1.0000x reference)
#include <cuda_runtime.h>
#include <cstdint>

// ---------------------------------------------------------------------------
// Decoder_31791347925413
//   Inputs (metadata order):
//     0 lighting (N,17)  1 mel (N,1,64,64)  2 blood  3 shade  4 spec (N,3,64,64)
//     5 illA (33)  6 illF (33,12)  7 pcaMeans (99)  8 pcaComponents (99,2)
//     9 skinColor (1,33,256,256)  10 tmatrix (1,9,128,128)
//   Output: concat(rgb[N,3,HW], shade[N,HW], spec[N,3,HW], blood[N,HW],
//                  mel[N,HW], b[N,2], raw[N,3,HW]) as float32
// ---------------------------------------------------------------------------

#define MAX_N 512

// Scratch (static __device__ arrays: the sanctioned no-alloc workaround)
__device__ float g_skinT[256 * 256 * 36];    // channels-last, padded 33->36
__device__ float g_params[MAX_N * 128];      // per-sample folded constants

__constant__ float cS0[33] = {94.8f,104.8f,105.9f,96.8f,113.9f,125.6f,125.5f,121.3f,121.3f,113.5f,113.1f,110.8f,106.5f,108.8f,105.3f,104.4f,100.0f,96.0f,95.1f,89.1f,90.5f,90.3f,88.4f,84.0f,85.1f,81.9f,82.6f,84.9f,81.3f,71.9f,74.3f,76.4f,63.3f};
__constant__ float cS1[33] = {43.4f,46.3f,43.9f,37.1f,36.7f,35.9f,32.6f,27.9f,24.3f,20.1f,16.2f,13.2f,8.6f,6.1f,4.2f,1.9f,0.0f,-1.6f,-3.5f,-3.5f,-5.8f,-7.2f,-8.6f,-9.5f,-10.9f,-10.7f,-12.0f,-14.0f,-13.6f,-12.0f,-13.3f,-12.9f,-10.6f};
__constant__ float cS2[33] = {-1.1f,-0.5f,-0.7f,-1.2f,-2.6f,-2.9f,-2.8f,-2.6f,-2.6f,-1.8f,-1.5f,-1.3f,-1.2f,-1.0f,-0.5f,-0.3f,0.0f,0.2f,0.5f,2.1f,3.2f,4.1f,4.7f,5.1f,6.7f,7.3f,8.6f,9.8f,10.2f,8.3f,9.6f,8.5f,7.0f};
__constant__ float cXYZ[9] = {3.2406f,-1.537f,-0.498f, -0.968f,1.8758f,0.0415f, 0.0557f,-0.204f,1.057f};

// ---------------------------------------------------------------------------
// Kernel T: transpose skinColor (33,256,256) -> channels-last padded (65536,36)
// Block handles 64 positions; smem tile [64][33]; both phases coalesced.
// ---------------------------------------------------------------------------
__global__ void __launch_bounds__(256) k_transpose(const float* __restrict__ skin)
{
    __shared__ float tile[64][33];
    int base = blockIdx.x * 64;
    for (int idx = threadIdx.x; idx < 33 * 64; idx += blockDim.x) {
        int k = idx >> 6;          // channel
        int p = idx & 63;          // position within block
        tile[p][k] = __ldg(skin + k * 65536 + base + p);
    }
    __syncthreads();
    for (int idx = threadIdx.x; idx < 64 * 36; idx += blockDim.x) {
        int p = idx / 36;
        int k = idx - p * 36;
        g_skinT[(base + p) * 36 + k] = (k < 33) ? tile[p][k] : 0.0f;
    }
}

// ---------------------------------------------------------------------------
// Kernel P: per-sample folded constants. One thread per sample (N small).
//   g_params[n*128 + ...]:
//     [0..107]   eS[c][k] = e_norm[k]*S[c][k]  (3 x 36, zero-padded)
//     [108..110] lightColor[c]
//     [111..119] M2[o][c] = (XYZ2RGB . T^T)[o][c] / lightColor[c]
//   Also writes the `b` output section.
// ---------------------------------------------------------------------------
__global__ void k_params(const float* __restrict__ lighting,
                         const float* __restrict__ illA,
                         const float* __restrict__ illF,
                         const float* __restrict__ pcaMeans,
                         const float* __restrict__ pcaComp,
                         const float* __restrict__ tmat,
                         float* __restrict__ out_b, int N)
{
    int n = blockIdx.x * blockDim.x + threadIdx.x;
    if (n >= N) return;
    const float* L = lighting + n * 17;

    // softmax over L[0..13]
    float lp[15];
    #pragma unroll
    for (int i = 0; i < 15; i++) lp[i] = L[i];
    float mx = lp[0];
    #pragma unroll
    for (int i = 1; i < 14; i++) mx = fmaxf(mx, lp[i]);
    float lw[14]; float s = 0.0f;
    #pragma unroll
    for (int i = 0; i < 14; i++) { lw[i] = expf(lp[i] - mx); s += lw[i]; }
    float inv = 1.0f / s;
    float wA = lw[0] * inv, wD = lw[1] * inv;
    float fW[12];
    #pragma unroll
    for (int j = 0; j < 12; j++) fW[j] = lw[2 + j] * inv;

    float ct = 1.0f / (1.0f + expf(-lp[14]));
    float b0 = 6.0f / (1.0f + expf(-L[15])) - 3.0f;
    float b1 = 6.0f / (1.0f + expf(-L[16])) - 3.0f;
    out_b[2 * n + 0] = b0;
    out_b[2 * n + 1] = b1;

    // illuminance_d
    float t = ct * 21000.0f + 4000.0f;
    float it = 1.0f / t, it2 = it * it, it3 = it2 * it;
    float x = (t <= 7000.0f)
        ? (-4.607e9f * it3 + 2.9678e6f * it2 + 99.11f * it + 0.244063f)
        : (-2.0064e9f * it3 + 1.9018e6f * it2 + 247.48f * it + 0.23704f);
    float y  = -3.0f * x * x + 2.87f * x - 0.275f;
    float mm = 0.0241f + 0.2562f * x - 0.7341f * y;
    float m1 = (-1.3515f - 1.7703f * x + 5.9114f * y) / mm;
    float m2 = (0.03f - 31.4424f * x + 30.0717f * y) / mm;

    float D[33]; float ds = 0.0f;
    #pragma unroll
    for (int k = 0; k < 33; k++) { D[k] = cS0[k] + m1 * cS1[k] + m2 * cS2[k]; ds += D[k]; }
    float dsi = 1.0f / ds;

    // e and its normalization
    float e[33]; float es = 0.0f;
    #pragma unroll
    for (int k = 0; k < 33; k++) {
        float v = wA * illA[k] + wD * D[k] * dsi;
        #pragma unroll
        for (int j = 0; j < 12; j++) v += fW[j] * illF[k * 12 + j];
        e[k] = v; es += v;
    }
    float esi = 1.0f / es;

    // S, lightColor, eS
    float* P = g_params + n * 128;
    float lc[3];
    #pragma unroll
    for (int c = 0; c < 3; c++) {
        float acc = 0.0f;
        #pragma unroll
        for (int k = 0; k < 33; k++) {
            int j = c * 33 + k;
            float Sv = fmaxf(0.0f, b0 * pcaComp[2 * j] + b1 * pcaComp[2 * j + 1] + pcaMeans[j]);
            acc += Sv;
            P[c * 36 + k] = e[k] * esi * Sv;
        }
        P[c * 36 + 33] = 0.0f; P[c * 36 + 34] = 0.0f; P[c * 36 + 35] = 0.0f;
        lc[c] = acc;
        P[108 + c] = acc;
    }

    // tmatrix bilinear at (b0/3, b1/3), W=H=128, align-corners formula
    float fx = (b0 * (1.0f / 3.0f) + 1.0f) * (0.5f * 127.0f);
    float fy = (b1 * (1.0f / 3.0f) + 1.0f) * (0.5f * 127.0f);
    float x0f = floorf(fx), y0f = floorf(fy);
    float wx = fx - x0f, wy = fy - y0f;
    int ix0 = min(max((int)x0f, 0), 127), iy0 = min(max((int)y0f, 0), 127);
    int ix1 = min(ix0 + 1, 127),          iy1 = min(iy0 + 1, 127);
    float w00 = (1.0f - wx) * (1.0f - wy), w01 = wx * (1.0f - wy);
    float w10 = (1.0f - wx) * wy,          w11 = wx * wy;
    float T[9];
    #pragma unroll
    for (int i = 0; i < 9; i++) {
        const float* bp = tmat + i * 16384;
        T[i] = w00 * bp[iy0 * 128 + ix0] + w01 * bp[iy0 * 128 + ix1]
             + w10 * bp[iy1 * 128 + ix0] + w11 * bp[iy1 * 128 + ix1];
    }
    // M2[o][c] = (sum_o2 XYZ2RGB[o][o2] * T[c*3+o2]) / lc[c]
    #pragma unroll
    for (int o = 0; o < 3; o++)
        #pragma unroll
        for (int c = 0; c < 3; c++) {
            float v = cXYZ[o * 3 + 0] * T[c * 3 + 0]
                    + cXYZ[o * 3 + 1] * T[c * 3 + 1]
                    + cXYZ[o * 3 + 2] * T[c * 3 + 2];
            P[111 + o * 3 + c] = v / lc[c];
        }
}

// ---------------------------------------------------------------------------
// Kernel M: per-pixel main. Thread per pixel. grid = (HW/256, N).
// ---------------------------------------------------------------------------
__global__ void __launch_bounds__(256) k_main(
    const float* __restrict__ mel_in, const float* __restrict__ blood_in,
    const float* __restrict__ shade_in, const float* __restrict__ spec_in,
    float* __restrict__ out, int N, int HW)
{
    __shared__ float sP[120];
    int n = blockIdx.y;
    {
        const float* P = g_params + n * 128;
        for (int i = threadIdx.x; i < 120; i += blockDim.x) sP[i] = P[i];
    }
    __syncthreads();

    int pix = blockIdx.x * blockDim.x + threadIdx.x;
    if (pix >= HW) return;
    size_t idx = (size_t)n * HW + pix;

    float m  = mel_in[idx];
    float bl = blood_in[idx];
    float sh = shade_in[idx];

    m  = 2.0f * __fdividef(1.0f, 1.0f + __expf(-m))  - 1.0f;  // 2*sigmoid-1
    bl = 2.0f * __fdividef(1.0f, 1.0f + __expf(-bl)) - 1.0f;
    sh = __expf(sh);

    const float* sp_ptr = spec_in + (size_t)n * 3 * HW + pix;
    float sp0 = __expf(sp_ptr[0])      * sP[108];
    float sp1 = __expf(sp_ptr[HW])     * sP[109];
    float sp2 = __expf(sp_ptr[2 * HW]) * sP[110];

    // grid_sample coords into 256x256 LUT (x from mel, y from blood)
    float fx = (m  + 1.0f) * (0.5f * 255.0f);
    float fy = (bl + 1.0f) * (0.5f * 255.0f);
    float x0f = floorf(fx), y0f = floorf(fy);
    float wx = fx - x0f, wy = fy - y0f;
    int ix0 = min(max((int)x0f, 0), 255), iy0 = min(max((int)y0f, 0), 255);
    int ix1 = min(ix0 + 1, 255),          iy1 = min(iy0 + 1, 255);
    float w00 = (1.0f - wx) * (1.0f - wy), w01 = wx * (1.0f - wy);
    float w10 = (1.0f - wx) * wy,          w11 = wx * wy;

    const float4* p00 = reinterpret_cast<const float4*>(g_skinT + (iy0 * 256 + ix0) * 36);
    const float4* p01 = reinterpret_cast<const float4*>(g_skinT + (iy0 * 256 + ix1) * 36);
    const float4* p10 = reinterpret_cast<const float4*>(g_skinT + (iy1 * 256 + ix0) * 36);
    const float4* p11 = reinterpret_cast<const float4*>(g_skinT + (iy1 * 256 + ix1) * 36);

    float d0 = 0.0f, d1 = 0.0f, d2 = 0.0f;
    #pragma unroll
    for (int q = 0; q < 9; q++) {
        float4 a = __ldg(p00 + q);
        float4 b = __ldg(p01 + q);
        float4 c = __ldg(p10 + q);
        float4 d = __ldg(p11 + q);
        float r0 = w00 * a.x + w01 * b.x + w10 * c.x + w11 * d.x;
        float r1 = w00 * a.y + w01 * b.y + w10 * c.y + w11 * d.y;
        float r2 = w00 * a.z + w01 * b.z + w10 * c.z + w11 * d.z;
        float r3 = w00 * a.w + w01 * b.w + w10 * c.w + w11 * d.w;
        int k = q * 4;
        d0 += r0 * sP[k]      + r1 * sP[k + 1]      + r2 * sP[k + 2]      + r3 * sP[k + 3];
        d1 += r0 * sP[36 + k] + r1 * sP[36 + k + 1] + r2 * sP[36 + k + 2] + r3 * sP[36 + k + 3];
        d2 += r0 * sP[72 + k] + r1 * sP[72 + k + 1] + r2 * sP[72 + k + 2] + r3 * sP[72 + k + 3];
    }

    float raw0 = sh * d0 + sp0;
    float raw1 = sh * d1 + sp1;
    float raw2 = sh * d2 + sp2;

    float rgb0 = fmaxf(0.0f, sP[111] * raw0 + sP[112] * raw1 + sP[113] * raw2);
    float rgb1 = fmaxf(0.0f, sP[114] * raw0 + sP[115] * raw1 + sP[116] * raw2);
    float rgb2 = fmaxf(0.0f, sP[117] * raw0 + sP[118] * raw1 + sP[119] * raw2);

    // Output layout: rgb | shade | spec | blood | mel | b | raw
    size_t plane = (size_t)N * HW;
    size_t o3 = (size_t)n * 3 * HW + pix;
    out[o3]          = rgb0;
    out[o3 + HW]     = rgb1;
    out[o3 + 2 * HW] = rgb2;
    out[3 * plane + idx] = sh;
    float* ospec = out + 4 * plane;
    ospec[o3]          = sp0;
    ospec[o3 + HW]     = sp1;
    ospec[o3 + 2 * HW] = sp2;
    out[7 * plane + idx] = bl;
    out[8 * plane + idx] = m;
    float* oraw = out + 9 * plane + 2 * (size_t)N;
    oraw[o3]          = raw0;
    oraw[o3 + HW]     = raw1;
    oraw[o3 + 2 * HW] = raw2;
}

// ---------------------------------------------------------------------------
extern "C" void kernel_launch(void* const* d_in, const int* in_sizes, int n_in,
                              void* d_out, int out_size)
{
    const float* lighting = (const float*)d_in[0];
    const float* mel      = (const float*)d_in[1];
    const float* blood    = (const float*)d_in[2];
    const float* shade    = (const float*)d_in[3];
    const float* spec     = (const float*)d_in[4];
    const float* illA     = (const float*)d_in[5];
    const float* illF     = (const float*)d_in[6];
    const float* pcaMeans = (const float*)d_in[7];
    const float* pcaComp  = (const float*)d_in[8];
    const float* skin     = (const float*)d_in[9];
    const float* tmat     = (const float*)d_in[10];

    int N  = in_sizes[0] / 17;          // lighting is (N, 17)
    if (N > MAX_N) N = MAX_N;           // hard cap (scratch bound)
    int HW = in_sizes[1] / N;           // mel is (N, 1, size, size)
    size_t plane = (size_t)N * HW;
    float* out = (float*)d_out;

    k_transpose<<<1024, 256>>>(skin);
    k_params<<<(N + 127) / 128, 128>>>(lighting, illA, illF, pcaMeans, pcaComp,
                                       tmat, out + 9 * plane, N);
    dim3 grid((HW + 255) / 256, N);
    k_main<<<grid, 256>>>(mel, blood, shade, spec, out, N, HW);
}

// round 4
// speedup vs baseline: 1.3260x; 1.3260x over previous
#include <cuda_runtime.h>
#include <cuda_fp16.h>
#include <cstdint>

// ---------------------------------------------------------------------------
// Decoder_31791347925413
//   Output: concat(rgb[N,3,HW], shade[N,HW], spec[N,3,HW], blood[N,HW],
//                  mel[N,HW], b[N,2], raw[N,3,HW]) as float32
// Strategy: LUT transposed to channels-last __half padded 33->40 (80B rows,
// 5 x uint4 per bilinear corner). L1tex wavefronts: 20/pixel (was 36).
// ---------------------------------------------------------------------------

#define MAX_N 512

__device__ __half g_skinH[256 * 256 * 40];   // channels-last fp16 LUT
__device__ float  g_params[MAX_N * 144];     // per-sample folded constants

__constant__ float cS0[33] = {94.8f,104.8f,105.9f,96.8f,113.9f,125.6f,125.5f,121.3f,121.3f,113.5f,113.1f,110.8f,106.5f,108.8f,105.3f,104.4f,100.0f,96.0f,95.1f,89.1f,90.5f,90.3f,88.4f,84.0f,85.1f,81.9f,82.6f,84.9f,81.3f,71.9f,74.3f,76.4f,63.3f};
__constant__ float cS1[33] = {43.4f,46.3f,43.9f,37.1f,36.7f,35.9f,32.6f,27.9f,24.3f,20.1f,16.2f,13.2f,8.6f,6.1f,4.2f,1.9f,0.0f,-1.6f,-3.5f,-3.5f,-5.8f,-7.2f,-8.6f,-9.5f,-10.9f,-10.7f,-12.0f,-14.0f,-13.6f,-12.0f,-13.3f,-12.9f,-10.6f};
__constant__ float cS2[33] = {-1.1f,-0.5f,-0.7f,-1.2f,-2.6f,-2.9f,-2.8f,-2.6f,-2.6f,-1.8f,-1.5f,-1.3f,-1.2f,-1.0f,-0.5f,-0.3f,0.0f,0.2f,0.5f,2.1f,3.2f,4.1f,4.7f,5.1f,6.7f,7.3f,8.6f,9.8f,10.2f,8.3f,9.6f,8.5f,7.0f};
__constant__ float cXYZ[9] = {3.2406f,-1.537f,-0.498f, -0.968f,1.8758f,0.0415f, 0.0557f,-0.204f,1.057f};

// ---------------------------------------------------------------------------
// Kernel T: transpose skinColor (33,256,256) -> channels-last fp16 (65536,40)
// ---------------------------------------------------------------------------
__global__ void __launch_bounds__(256) k_transpose(const float* __restrict__ skin)
{
    __shared__ float tile[64][33];
    int base = blockIdx.x * 64;
    for (int idx = threadIdx.x; idx < 33 * 64; idx += blockDim.x) {
        int k = idx >> 6;          // channel
        int p = idx & 63;          // position within block
        tile[p][k] = __ldg(skin + k * 65536 + base + p);
    }
    __syncthreads();
    for (int idx = threadIdx.x; idx < 64 * 40; idx += blockDim.x) {
        int p = idx / 40;
        int k = idx - p * 40;
        g_skinH[(size_t)(base + p) * 40 + k] =
            (k < 33) ? __float2half_rn(tile[p][k]) : __half(0.0f);
    }
}

// ---------------------------------------------------------------------------
// Kernel P: per-sample folded constants. One thread per sample.
//   g_params[n*144 + ...]:
//     [0..119]   eS[c][k] = e_norm[k]*S[c][k]  (3 x 40, zero-padded)
//     [120..122] lightColor[c]
//     [123..131] M2[o][c] = (XYZ2RGB . T^T)[o][c] / lightColor[c]
// ---------------------------------------------------------------------------
__global__ void k_params(const float* __restrict__ lighting,
                         const float* __restrict__ illA,
                         const float* __restrict__ illF,
                         const float* __restrict__ pcaMeans,
                         const float* __restrict__ pcaComp,
                         const float* __restrict__ tmat,
                         float* __restrict__ out_b, int N)
{
    int n = blockIdx.x * blockDim.x + threadIdx.x;
    if (n >= N) return;
    const float* L = lighting + n * 17;

    float lp[15];
    #pragma unroll
    for (int i = 0; i < 15; i++) lp[i] = L[i];
    float mx = lp[0];
    #pragma unroll
    for (int i = 1; i < 14; i++) mx = fmaxf(mx, lp[i]);
    float lw[14]; float s = 0.0f;
    #pragma unroll
    for (int i = 0; i < 14; i++) { lw[i] = expf(lp[i] - mx); s += lw[i]; }
    float inv = 1.0f / s;
    float wA = lw[0] * inv, wD = lw[1] * inv;
    float fW[12];
    #pragma unroll
    for (int j = 0; j < 12; j++) fW[j] = lw[2 + j] * inv;

    float ct = 1.0f / (1.0f + expf(-lp[14]));
    float b0 = 6.0f / (1.0f + expf(-L[15])) - 3.0f;
    float b1 = 6.0f / (1.0f + expf(-L[16])) - 3.0f;
    out_b[2 * n + 0] = b0;
    out_b[2 * n + 1] = b1;

    float t = ct * 21000.0f + 4000.0f;
    float it = 1.0f / t, it2 = it * it, it3 = it2 * it;
    float x = (t <= 7000.0f)
        ? (-4.607e9f * it3 + 2.9678e6f * it2 + 99.11f * it + 0.244063f)
        : (-2.0064e9f * it3 + 1.9018e6f * it2 + 247.48f * it + 0.23704f);
    float y  = -3.0f * x * x + 2.87f * x - 0.275f;
    float mm = 0.0241f + 0.2562f * x - 0.7341f * y;
    float m1 = (-1.3515f - 1.7703f * x + 5.9114f * y) / mm;
    float m2 = (0.03f - 31.4424f * x + 30.0717f * y) / mm;

    float D[33]; float ds = 0.0f;
    #pragma unroll
    for (int k = 0; k < 33; k++) { D[k] = cS0[k] + m1 * cS1[k] + m2 * cS2[k]; ds += D[k]; }
    float dsi = 1.0f / ds;

    float e[33]; float es = 0.0f;
    #pragma unroll
    for (int k = 0; k < 33; k++) {
        float v = wA * illA[k] + wD * D[k] * dsi;
        #pragma unroll
        for (int j = 0; j < 12; j++) v += fW[j] * illF[k * 12 + j];
        e[k] = v; es += v;
    }
    float esi = 1.0f / es;

    float* P = g_params + n * 144;
    float lc[3];
    #pragma unroll
    for (int c = 0; c < 3; c++) {
        float acc = 0.0f;
        #pragma unroll
        for (int k = 0; k < 33; k++) {
            int j = c * 33 + k;
            float Sv = fmaxf(0.0f, b0 * pcaComp[2 * j] + b1 * pcaComp[2 * j + 1] + pcaMeans[j]);
            acc += Sv;
            P[c * 40 + k] = e[k] * esi * Sv;
        }
        #pragma unroll
        for (int k = 33; k < 40; k++) P[c * 40 + k] = 0.0f;
        lc[c] = acc;
        P[120 + c] = acc;
    }

    // tmatrix bilinear at (b0/3, b1/3), W=H=128, align-corners formula
    float fx = (b0 * (1.0f / 3.0f) + 1.0f) * (0.5f * 127.0f);
    float fy = (b1 * (1.0f / 3.0f) + 1.0f) * (0.5f * 127.0f);
    float x0f = floorf(fx), y0f = floorf(fy);
    float wx = fx - x0f, wy = fy - y0f;
    int ix0 = min(max((int)x0f, 0), 127), iy0 = min(max((int)y0f, 0), 127);
    int ix1 = min(ix0 + 1, 127),          iy1 = min(iy0 + 1, 127);
    float w00 = (1.0f - wx) * (1.0f - wy), w01 = wx * (1.0f - wy);
    float w10 = (1.0f - wx) * wy,          w11 = wx * wy;
    float T[9];
    #pragma unroll
    for (int i = 0; i < 9; i++) {
        const float* bp = tmat + i * 16384;
        T[i] = w00 * bp[iy0 * 128 + ix0] + w01 * bp[iy0 * 128 + ix1]
             + w10 * bp[iy1 * 128 + ix0] + w11 * bp[iy1 * 128 + ix1];
    }
    #pragma unroll
    for (int o = 0; o < 3; o++)
        #pragma unroll
        for (int c = 0; c < 3; c++) {
            float v = cXYZ[o * 3 + 0] * T[c * 3 + 0]
                    + cXYZ[o * 3 + 1] * T[c * 3 + 1]
                    + cXYZ[o * 3 + 2] * T[c * 3 + 2];
            P[123 + o * 3 + c] = v / lc[c];
        }
}

// ---------------------------------------------------------------------------
// Kernel M: per-pixel main. Thread per pixel. grid = (HW/256, N).
// 20 x LDG.128 gather per pixel from fp16 channels-last LUT.
// ---------------------------------------------------------------------------
__global__ void __launch_bounds__(256) k_main(
    const float* __restrict__ mel_in, const float* __restrict__ blood_in,
    const float* __restrict__ shade_in, const float* __restrict__ spec_in,
    float* __restrict__ out, int N, int HW)
{
    __shared__ float sP[132];
    int n = blockIdx.y;
    {
        const float* P = g_params + n * 144;
        for (int i = threadIdx.x; i < 132; i += blockDim.x) sP[i] = P[i];
    }
    __syncthreads();

    int pix = blockIdx.x * blockDim.x + threadIdx.x;
    if (pix >= HW) return;
    size_t idx = (size_t)n * HW + pix;

    float m  = mel_in[idx];
    float bl = blood_in[idx];
    float sh = shade_in[idx];

    m  = 2.0f * __fdividef(1.0f, 1.0f + __expf(-m))  - 1.0f;  // 2*sigmoid-1
    bl = 2.0f * __fdividef(1.0f, 1.0f + __expf(-bl)) - 1.0f;
    sh = __expf(sh);

    const float* sp_ptr = spec_in + (size_t)n * 3 * HW + pix;
    float sp0 = __expf(sp_ptr[0])      * sP[120];
    float sp1 = __expf(sp_ptr[HW])     * sP[121];
    float sp2 = __expf(sp_ptr[2 * HW]) * sP[122];

    // grid_sample coords into 256x256 LUT (x from mel, y from blood)
    float fx = (m  + 1.0f) * (0.5f * 255.0f);
    float fy = (bl + 1.0f) * (0.5f * 255.0f);
    float x0f = floorf(fx), y0f = floorf(fy);
    float wx = fx - x0f, wy = fy - y0f;
    int ix0 = min(max((int)x0f, 0), 255), iy0 = min(max((int)y0f, 0), 255);
    int ix1 = min(ix0 + 1, 255),          iy1 = min(iy0 + 1, 255);
    float w00 = (1.0f - wx) * (1.0f - wy), w01 = wx * (1.0f - wy);
    float w10 = (1.0f - wx) * wy,          w11 = wx * wy;

    const uint4* p00 = reinterpret_cast<const uint4*>(g_skinH + (size_t)(iy0 * 256 + ix0) * 40);
    const uint4* p01 = reinterpret_cast<const uint4*>(g_skinH + (size_t)(iy0 * 256 + ix1) * 40);
    const uint4* p10 = reinterpret_cast<const uint4*>(g_skinH + (size_t)(iy1 * 256 + ix0) * 40);
    const uint4* p11 = reinterpret_cast<const uint4*>(g_skinH + (size_t)(iy1 * 256 + ix1) * 40);

    float d0 = 0.0f, d1 = 0.0f, d2 = 0.0f;
    #pragma unroll
    for (int q = 0; q < 5; q++) {
        uint4 A = __ldg(p00 + q);
        uint4 B = __ldg(p01 + q);
        uint4 C = __ldg(p10 + q);
        uint4 D = __ldg(p11 + q);
        const unsigned* au = &A.x; const unsigned* bu = &B.x;
        const unsigned* cu = &C.x; const unsigned* du = &D.x;
        #pragma unroll
        for (int h = 0; h < 4; h++) {          // each unsigned = 2 halves
            float2 a = __half22float2(*reinterpret_cast<const __half2*>(au + h));
            float2 b = __half22float2(*reinterpret_cast<const __half2*>(bu + h));
            float2 c = __half22float2(*reinterpret_cast<const __half2*>(cu + h));
            float2 d = __half22float2(*reinterpret_cast<const __half2*>(du + h));
            float r0 = w00 * a.x + w01 * b.x + w10 * c.x + w11 * d.x;
            float r1 = w00 * a.y + w01 * b.y + w10 * c.y + w11 * d.y;
            int k = q * 8 + h * 2;
            d0 += r0 * sP[k]      + r1 * sP[k + 1];
            d1 += r0 * sP[40 + k] + r1 * sP[40 + k + 1];
            d2 += r0 * sP[80 + k] + r1 * sP[80 + k + 1];
        }
    }

    float raw0 = sh * d0 + sp0;
    float raw1 = sh * d1 + sp1;
    float raw2 = sh * d2 + sp2;

    float rgb0 = fmaxf(0.0f, sP[123] * raw0 + sP[124] * raw1 + sP[125] * raw2);
    float rgb1 = fmaxf(0.0f, sP[126] * raw0 + sP[127] * raw1 + sP[128] * raw2);
    float rgb2 = fmaxf(0.0f, sP[129] * raw0 + sP[130] * raw1 + sP[131] * raw2);

    // Output layout: rgb | shade | spec | blood | mel | b | raw
    size_t plane = (size_t)N * HW;
    size_t o3 = (size_t)n * 3 * HW + pix;
    out[o3]          = rgb0;
    out[o3 + HW]     = rgb1;
    out[o3 + 2 * HW] = rgb2;
    out[3 * plane + idx] = sh;
    float* ospec = out + 4 * plane;
    ospec[o3]          = sp0;
    ospec[o3 + HW]     = sp1;
    ospec[o3 + 2 * HW] = sp2;
    out[7 * plane + idx] = bl;
    out[8 * plane + idx] = m;
    float* oraw = out + 9 * plane + 2 * (size_t)N;
    oraw[o3]          = raw0;
    oraw[o3 + HW]     = raw1;
    oraw[o3 + 2 * HW] = raw2;
}

// ---------------------------------------------------------------------------
extern "C" void kernel_launch(void* const* d_in, const int* in_sizes, int n_in,
                              void* d_out, int out_size)
{
    const float* lighting = (const float*)d_in[0];
    const float* mel      = (const float*)d_in[1];
    const float* blood    = (const float*)d_in[2];
    const float* shade    = (const float*)d_in[3];
    const float* spec     = (const float*)d_in[4];
    const float* illA     = (const float*)d_in[5];
    const float* illF     = (const float*)d_in[6];
    const float* pcaMeans = (const float*)d_in[7];
    const float* pcaComp  = (const float*)d_in[8];
    const float* skin     = (const float*)d_in[9];
    const float* tmat     = (const float*)d_in[10];

    int N  = in_sizes[0] / 17;          // lighting is (N, 17)
    if (N > MAX_N) N = MAX_N;
    int HW = in_sizes[1] / N;           // mel is (N, 1, size, size)
    size_t plane = (size_t)N * HW;
    float* out = (float*)d_out;

    k_transpose<<<1024, 256>>>(skin);
    k_params<<<(N + 127) / 128, 128>>>(lighting, illA, illF, pcaMeans, pcaComp,
                                       tmat, out + 9 * plane, N);
    dim3 grid((HW + 255) / 256, N);
    k_main<<<grid, 256>>>(mel, blood, shade, spec, out, N, HW);
}